// round 1
// baseline (speedup 1.0000x reference)
#include <cuda_runtime.h>
#include <cstdint>

#define BN 64
#define PP 8732
#define CC 81
#define KT 16
#define THRESH 0.5f
#define VAR0 0.1f
#define VAR1 0.2f

// ---------------- scratch (no allocations allowed) ----------------
__device__ float g_bto[BN * PP];    // best truth overlap per prior
__device__ int   g_bti[BN * PP];    // best truth idx per prior
__device__ int   g_conf_t[BN * PP]; // matched class (0 = background)
__device__ float g_ce[BN * PP];     // per-prior cross-entropy
__device__ float g_loss_l[BN];
__device__ float g_loss_c[BN];
__device__ int   g_num_pos[BN];

// ---------------- kernel 1: match + smooth-L1 ----------------
__global__ void k_match(const float* __restrict__ loc,
                        const float* __restrict__ priors,
                        const float* __restrict__ targets) {
    const int b = blockIdx.x;
    const int tid = threadIdx.x;

    __shared__ float s_t[KT][4];
    __shared__ float s_area[KT];
    __shared__ int   s_lab[KT];
    __shared__ unsigned long long s_best[KT];
    __shared__ float s_redf[256];
    __shared__ int   s_redi[256];

    if (tid < KT) {
        const float* tg = targets + (size_t)(b * KT + tid) * 6;
        s_lab[tid] = (int)tg[1];
        s_t[tid][0] = tg[2]; s_t[tid][1] = tg[3];
        s_t[tid][2] = tg[4]; s_t[tid][3] = tg[5];
        s_area[tid] = (tg[4] - tg[2]) * (tg[5] - tg[3]);
        s_best[tid] = 0ull;
    }
    __syncthreads();

    unsigned long long lbest[KT];
#pragma unroll
    for (int k = 0; k < KT; k++) lbest[k] = 0ull;

    // phase A: per-prior best truth; per-truth best prior (local)
    for (int p = tid; p < PP; p += blockDim.x) {
        const float px1 = priors[4 * p + 0], py1 = priors[4 * p + 1];
        const float px2 = priors[4 * p + 2], py2 = priors[4 * p + 3];
        const float parea = (px2 - px1) * (py2 - py1);
        float bestov = -1.0f;
        int besti = 0;
#pragma unroll
        for (int k = 0; k < KT; k++) {
            float ix1 = fmaxf(s_t[k][0], px1);
            float iy1 = fmaxf(s_t[k][1], py1);
            float ix2 = fminf(s_t[k][2], px2);
            float iy2 = fminf(s_t[k][3], py2);
            float iw = fmaxf(ix2 - ix1, 0.0f);
            float ih = fmaxf(iy2 - iy1, 0.0f);
            float inter = iw * ih;
            float ov = inter / (s_area[k] + parea - inter);
            if (ov > bestov) { bestov = ov; besti = k; }  // first-max wins
            // key: higher overlap wins; tie -> lower prior index (first occurrence)
            unsigned long long key =
                ((unsigned long long)__float_as_uint(ov) << 32) |
                (unsigned long long)(0xFFFFFFFFu - (unsigned)p);
            if (key > lbest[k]) lbest[k] = key;
        }
        g_bto[b * PP + p] = bestov;
        g_bti[b * PP + p] = besti;
    }
#pragma unroll
    for (int k = 0; k < KT; k++)
        atomicMax(&s_best[k], lbest[k]);
    __syncthreads();

    // sequential force-assign (last write wins, like the reference scatter)
    if (tid == 0) {
        for (int k = 0; k < KT; k++) {
            unsigned long long key = s_best[k];
            int p = (int)(0xFFFFFFFFu - (unsigned)(key & 0xFFFFFFFFull));
            float ov = __uint_as_float((unsigned)(key >> 32));
            g_bti[b * PP + p] = k;
            g_bto[b * PP + p] = ov;
        }
    }
    __syncthreads();

    // phase B: conf_t + smooth-L1 over positives
    float lsum = 0.0f;
    int lcnt = 0;
    for (int p = tid; p < PP; p += blockDim.x) {
        const float ov = g_bto[b * PP + p];
        const int k = g_bti[b * PP + p];
        const int ct = (ov < THRESH) ? 0 : s_lab[k];
        g_conf_t[b * PP + p] = ct;
        if (ct > 0) {
            lcnt++;
            const float px1 = priors[4 * p + 0], py1 = priors[4 * p + 1];
            const float px2 = priors[4 * p + 2], py2 = priors[4 * p + 3];
            const float pcx = 0.5f * (px1 + px2), pcy = 0.5f * (py1 + py2);
            const float pw = px2 - px1, ph = py2 - py1;
            const float mx1 = s_t[k][0], my1 = s_t[k][1];
            const float mx2 = s_t[k][2], my2 = s_t[k][3];
            float g0 = (0.5f * (mx1 + mx2) - pcx) / (VAR0 * pw);
            float g1 = (0.5f * (my1 + my2) - pcy) / (VAR0 * ph);
            float g2 = logf((mx2 - mx1) / pw) / VAR1;
            float g3 = logf((my2 - my1) / ph) / VAR1;
            const float* ld = loc + ((size_t)b * PP + p) * 4;
            float d, ad;
            d = ld[0] - g0; ad = fabsf(d); lsum += (ad < 1.0f) ? 0.5f * d * d : ad - 0.5f;
            d = ld[1] - g1; ad = fabsf(d); lsum += (ad < 1.0f) ? 0.5f * d * d : ad - 0.5f;
            d = ld[2] - g2; ad = fabsf(d); lsum += (ad < 1.0f) ? 0.5f * d * d : ad - 0.5f;
            d = ld[3] - g3; ad = fabsf(d); lsum += (ad < 1.0f) ? 0.5f * d * d : ad - 0.5f;
        }
    }
    // block reduce
    s_redf[tid] = lsum;
    s_redi[tid] = lcnt;
    __syncthreads();
    for (int s = 128; s > 0; s >>= 1) {
        if (tid < s) {
            s_redf[tid] += s_redf[tid + s];
            s_redi[tid] += s_redi[tid + s];
        }
        __syncthreads();
    }
    if (tid == 0) {
        g_loss_l[b] = s_redf[0];
        g_num_pos[b] = s_redi[0];
    }
}

// ---------------- kernel 2: per-prior cross-entropy (warp per prior) ----------------
__global__ void k_ce(const float* __restrict__ conf) {
    const int gw = (blockIdx.x * blockDim.x + threadIdx.x) >> 5;
    const int lane = threadIdx.x & 31;
    if (gw >= BN * PP) return;
    const int b = gw / PP;
    const int p = gw - b * PP;

    const float* row = conf + (size_t)b * PP * CC + (size_t)p * CC;
    const int tgt = g_conf_t[b * PP + p];

    const float x0 = row[lane];
    const float x1 = row[lane + 32];
    const bool h2 = (lane + 64) < CC;
    const float x2 = h2 ? row[lane + 64] : -3.402823466e38f;

    float m = fmaxf(x0, fmaxf(x1, x2));
#pragma unroll
    for (int o = 16; o; o >>= 1)
        m = fmaxf(m, __shfl_xor_sync(0xFFFFFFFFu, m, o));

    float s = expf(x0 - m) + expf(x1 - m) + (h2 ? expf(x2 - m) : 0.0f);
#pragma unroll
    for (int o = 16; o; o >>= 1)
        s += __shfl_xor_sync(0xFFFFFFFFu, s, o);

    float g = 0.0f;
    if (lane == tgt) g = x0;
    else if (lane + 32 == tgt) g = x1;
    else if (lane + 64 == tgt) g = x2;
#pragma unroll
    for (int o = 16; o; o >>= 1)
        g += __shfl_xor_sync(0xFFFFFFFFu, g, o);

    if (lane == 0)
        g_ce[b * PP + p] = m + logf(s) - g;
}

// ---------------- kernel 3: per-image hard-negative top-k sum (radix select) ----------------
__global__ void k_topk() {
    const int b = blockIdx.x;
    const int tid = threadIdx.x;
    const float* ce = g_ce + b * PP;
    const int* ct = g_conf_t + b * PP;

    __shared__ int s_hist[256];
    __shared__ unsigned s_prefix;
    __shared__ int s_rem;
    __shared__ float s_redf[256];
    __shared__ int s_redi[256];
    __shared__ float s_spos;

    // S_pos = sum of ce over positives
    float sp = 0.0f;
    for (int p = tid; p < PP; p += blockDim.x)
        if (ct[p] > 0) sp += ce[p];
    s_redf[tid] = sp;
    __syncthreads();
    for (int s = 128; s > 0; s >>= 1) {
        if (tid < s) s_redf[tid] += s_redf[tid + s];
        __syncthreads();
    }
    if (tid == 0) s_spos = s_redf[0];

    const int npos = g_num_pos[b];
    int k = 3 * npos;
    if (k > PP - 1) k = PP - 1;

    float T = 0.0f;
    if (k > 0) {
        if (tid == 0) { s_prefix = 0u; s_rem = k; }
        __syncthreads();
        for (int shift = 24; shift >= 0; shift -= 8) {
            s_hist[tid] = 0;
            __syncthreads();
            const unsigned pref = s_prefix;
            const unsigned hm = (shift == 24) ? 0u : (0xFFFFFFFFu << (shift + 8));
            for (int p = tid; p < PP; p += blockDim.x) {
                float lm = (ct[p] > 0) ? 0.0f : ce[p];
                unsigned bits = __float_as_uint(lm);
                if ((bits & hm) == pref)
                    atomicAdd(&s_hist[(bits >> shift) & 255], 1);
            }
            __syncthreads();
            if (tid == 0) {
                int rem = s_rem;
                int cum = 0;
                for (int i = 255; i >= 0; i--) {
                    cum += s_hist[i];
                    if (cum >= rem) {
                        s_prefix = pref | ((unsigned)i << shift);
                        s_rem = rem - (cum - s_hist[i]);
                        break;
                    }
                }
            }
            __syncthreads();
        }
        const unsigned t = s_prefix;
        float sumgt = 0.0f;
        int cntgt = 0;
        for (int p = tid; p < PP; p += blockDim.x) {
            float lm = (ct[p] > 0) ? 0.0f : ce[p];
            unsigned bits = __float_as_uint(lm);
            if (bits > t) { sumgt += lm; cntgt++; }
        }
        s_redf[tid] = sumgt;
        s_redi[tid] = cntgt;
        __syncthreads();
        for (int s = 128; s > 0; s >>= 1) {
            if (tid < s) {
                s_redf[tid] += s_redf[tid + s];
                s_redi[tid] += s_redi[tid + s];
            }
            __syncthreads();
        }
        T = s_redf[0] + (float)(k - s_redi[0]) * __uint_as_float(t);
    }
    if (tid == 0)
        g_loss_c[b] = s_spos + T;
}

// ---------------- kernel 4: finalize ----------------
__global__ void k_final(float* __restrict__ out) {
    const int tid = threadIdx.x;
    __shared__ float s_l[64], s_c[64];
    __shared__ int s_n[64];
    s_l[tid] = g_loss_l[tid];
    s_c[tid] = g_loss_c[tid];
    s_n[tid] = g_num_pos[tid];
    __syncthreads();
    for (int s = 32; s > 0; s >>= 1) {
        if (tid < s) {
            s_l[tid] += s_l[tid + s];
            s_c[tid] += s_c[tid + s];
            s_n[tid] += s_n[tid + s];
        }
        __syncthreads();
    }
    if (tid == 0) {
        float n = fmaxf((float)s_n[0], 1.0f);
        out[0] = s_l[0] / n;
        out[1] = s_c[0] / n;
    }
}

extern "C" void kernel_launch(void* const* d_in, const int* in_sizes, int n_in,
                              void* d_out, int out_size) {
    const float* loc = (const float*)d_in[0];
    const float* conf = (const float*)d_in[1];
    const float* priors = (const float*)d_in[2];
    const float* targets = (const float*)d_in[3];
    float* out = (float*)d_out;

    k_match<<<BN, 256>>>(loc, priors, targets);
    k_ce<<<(BN * PP + 7) / 8, 256>>>(conf);   // 8 warps/block, warp per prior
    k_topk<<<BN, 256>>>();
    k_final<<<1, 64>>>(out);
}

// round 2
// speedup vs baseline: 1.3169x; 1.3169x over previous
#include <cuda_runtime.h>
#include <cstdint>

#define BN 64
#define PP 8732
#define CC 81
#define KT 16
#define THRESH 0.5f
#define VAR0 0.1f
#define VAR1 0.2f

#define ROWS 128          // rows per k_ce block
#define NCHUNK 8          // prior chunks in k_matchA
#define CHUNK 1092        // ceil(PP/NCHUNK)

// ---------------- scratch ----------------
__device__ float g_bto[BN * PP];
__device__ int   g_bti[BN * PP];
__device__ int   g_conf_t[BN * PP];
__device__ float g_ce[BN * PP];
__device__ unsigned long long g_best[BN * KT];
__device__ float g_loss_l[BN];
__device__ float g_loss_c[BN];
__device__ int   g_num_pos[BN];

// ---------------- kernel 0: zero accumulators ----------------
__global__ void k_init() {
    const int tid = threadIdx.x;
    for (int i = tid; i < BN * KT; i += 256) g_best[i] = 0ull;
    if (tid < BN) { g_loss_l[tid] = 0.0f; g_num_pos[tid] = 0; }
}

// ---------------- kernel 1: overlaps + per-prior best truth + per-truth best prior ----------------
__global__ void k_matchA(const float* __restrict__ priors,
                         const float* __restrict__ targets) {
    const int b = blockIdx.x;
    const int c = blockIdx.y;
    const int tid = threadIdx.x;

    __shared__ float s_t[KT][4];
    __shared__ float s_area[KT];
    __shared__ unsigned long long s_best[KT];

    if (tid < KT) {
        const float* tg = targets + (size_t)(b * KT + tid) * 6;
        s_t[tid][0] = tg[2]; s_t[tid][1] = tg[3];
        s_t[tid][2] = tg[4]; s_t[tid][3] = tg[5];
        s_area[tid] = (tg[4] - tg[2]) * (tg[5] - tg[3]);
        s_best[tid] = 0ull;
    }
    __syncthreads();

    unsigned long long lbest[KT];
#pragma unroll
    for (int k = 0; k < KT; k++) lbest[k] = 0ull;

    const int p0 = c * CHUNK;
    const int p1 = (p0 + CHUNK < PP) ? p0 + CHUNK : PP;
    const float4* pri4 = (const float4*)priors;

    for (int p = p0 + tid; p < p1; p += blockDim.x) {
        const float4 pr = pri4[p];
        const float parea = (pr.z - pr.x) * (pr.w - pr.y);
        float bestov = -1.0f;
        int besti = 0;
#pragma unroll
        for (int k = 0; k < KT; k++) {
            float ix1 = fmaxf(s_t[k][0], pr.x);
            float iy1 = fmaxf(s_t[k][1], pr.y);
            float ix2 = fminf(s_t[k][2], pr.z);
            float iy2 = fminf(s_t[k][3], pr.w);
            float iw = fmaxf(ix2 - ix1, 0.0f);
            float ih = fmaxf(iy2 - iy1, 0.0f);
            float inter = iw * ih;
            float ov = inter / (s_area[k] + parea - inter);
            if (ov > bestov) { bestov = ov; besti = k; }
            unsigned long long key =
                ((unsigned long long)__float_as_uint(ov) << 32) |
                (unsigned long long)(0xFFFFFFFFu - (unsigned)p);
            if (key > lbest[k]) lbest[k] = key;
        }
        g_bto[b * PP + p] = bestov;
        g_bti[b * PP + p] = besti;
    }
#pragma unroll
    for (int k = 0; k < KT; k++)
        atomicMax(&s_best[k], lbest[k]);
    __syncthreads();
    if (tid < KT)
        atomicMax(&g_best[b * KT + tid], s_best[tid]);
}

// ---------------- kernel 2: sequential force-assign (last write wins over k) ----------------
__global__ void k_fix() {
    const int b = threadIdx.x;
    if (b >= BN) return;
    for (int k = 0; k < KT; k++) {
        unsigned long long key = g_best[b * KT + k];
        int p = (int)(0xFFFFFFFFu - (unsigned)(key & 0xFFFFFFFFull));
        float ov = __uint_as_float((unsigned)(key >> 32));
        g_bti[b * PP + p] = k;
        g_bto[b * PP + p] = ov;
    }
}

// ---------------- kernel 3: fused CE (thread-per-row, smem staged) + conf_t + smooth-L1 ----------------
__global__ __launch_bounds__(ROWS) void k_ce(const float* __restrict__ conf,
                                             const float* __restrict__ loc,
                                             const float* __restrict__ priors,
                                             const float* __restrict__ targets) {
    const int b = blockIdx.y;
    const int r0 = blockIdx.x * ROWS;
    const int tid = threadIdx.x;

    __shared__ float s_c[ROWS * CC];       // 41472 B
    __shared__ float s_t[KT][4];
    __shared__ int   s_lab[KT];
    __shared__ float s_redf[ROWS];
    __shared__ int   s_redi[ROWS];

    if (tid < KT) {
        const float* tg = targets + (size_t)(b * KT + tid) * 6;
        s_lab[tid] = (int)tg[1];
        s_t[tid][0] = tg[2]; s_t[tid][1] = tg[3];
        s_t[tid][2] = tg[4]; s_t[tid][3] = tg[5];
    }

    const int nvalid = (r0 + ROWS <= PP) ? ROWS : (PP - r0);
    const int nfl = nvalid * CC;
    const size_t base = ((size_t)b * PP + r0) * CC;   // divisible by 4
    const float4* c4 = (const float4*)(conf + base);
    const int nf4 = nfl >> 2;

#pragma unroll 4
    for (int i = tid; i < nf4; i += ROWS)
        ((float4*)s_c)[i] = c4[i];
    for (int i = (nf4 << 2) + tid; i < nfl; i += ROWS)
        s_c[i] = conf[base + i];
    __syncthreads();

    float lsum = 0.0f;
    int lcnt = 0;
    const int p = r0 + tid;
    if (tid < nvalid) {
        const float* row = s_c + tid * CC;
        // max (4-way ILP)
        float m0 = row[0], m1 = row[1], m2 = row[2], m3 = row[3];
        for (int i = 4; i + 3 < CC; i += 4) {
            m0 = fmaxf(m0, row[i]);
            m1 = fmaxf(m1, row[i + 1]);
            m2 = fmaxf(m2, row[i + 2]);
            m3 = fmaxf(m3, row[i + 3]);
        }
        m0 = fmaxf(m0, row[CC - 1]);           // CC = 81 = 4 + 76 + 1
        float m = fmaxf(fmaxf(m0, m1), fmaxf(m2, m3));
        // sum exp (4-way ILP)
        float s0 = 0.0f, s1 = 0.0f, s2 = 0.0f, s3 = 0.0f;
        for (int i = 0; i + 3 < CC; i += 4) {
            s0 += __expf(row[i] - m);
            s1 += __expf(row[i + 1] - m);
            s2 += __expf(row[i + 2] - m);
            s3 += __expf(row[i + 3] - m);
        }
        s0 += __expf(row[CC - 1] - m);
        const float lse = m + __logf(s0 + s1 + s2 + s3);

        const float ov = g_bto[b * PP + p];
        const int k = g_bti[b * PP + p];
        const int ct = (ov < THRESH) ? 0 : s_lab[k];
        g_conf_t[b * PP + p] = ct;
        g_ce[b * PP + p] = lse - row[ct];

        if (ct > 0) {
            lcnt = 1;
            const float4 pr = ((const float4*)priors)[p];
            const float pcx = 0.5f * (pr.x + pr.z), pcy = 0.5f * (pr.y + pr.w);
            const float pw = pr.z - pr.x, ph = pr.w - pr.y;
            const float mx1 = s_t[k][0], my1 = s_t[k][1];
            const float mx2 = s_t[k][2], my2 = s_t[k][3];
            float g0 = (0.5f * (mx1 + mx2) - pcx) / (VAR0 * pw);
            float g1 = (0.5f * (my1 + my2) - pcy) / (VAR0 * ph);
            float g2 = logf((mx2 - mx1) / pw) / VAR1;
            float g3 = logf((my2 - my1) / ph) / VAR1;
            const float4 ld = ((const float4*)loc)[(size_t)b * PP + p];
            float d, ad;
            d = ld.x - g0; ad = fabsf(d); lsum += (ad < 1.0f) ? 0.5f * d * d : ad - 0.5f;
            d = ld.y - g1; ad = fabsf(d); lsum += (ad < 1.0f) ? 0.5f * d * d : ad - 0.5f;
            d = ld.z - g2; ad = fabsf(d); lsum += (ad < 1.0f) ? 0.5f * d * d : ad - 0.5f;
            d = ld.w - g3; ad = fabsf(d); lsum += (ad < 1.0f) ? 0.5f * d * d : ad - 0.5f;
        }
    }
    s_redf[tid] = lsum;
    s_redi[tid] = lcnt;
    __syncthreads();
    for (int s = ROWS / 2; s > 0; s >>= 1) {
        if (tid < s) {
            s_redf[tid] += s_redf[tid + s];
            s_redi[tid] += s_redi[tid + s];
        }
        __syncthreads();
    }
    if (tid == 0) {
        if (s_redf[0] != 0.0f) atomicAdd(&g_loss_l[b], s_redf[0]);
        if (s_redi[0] != 0)    atomicAdd(&g_num_pos[b], s_redi[0]);
    }
}

// ---------------- kernel 4: per-image hard-negative top-k (radix select, smem resident) ----------------
__global__ void k_topk() {
    const int b = blockIdx.x;
    const int tid = threadIdx.x;

    __shared__ float s_lm[PP];       // 34928 B
    __shared__ int s_hist[256];
    __shared__ int s_cum[256];
    __shared__ unsigned s_prefix;
    __shared__ int s_rem;
    __shared__ float s_redf[256];
    __shared__ int s_redi[256];
    __shared__ float s_spos;

    float sp = 0.0f;
    for (int p = tid; p < PP; p += 256) {
        const float cev = g_ce[b * PP + p];
        const bool pos = g_conf_t[b * PP + p] > 0;
        if (pos) sp += cev;
        s_lm[p] = pos ? 0.0f : cev;
    }
    s_redf[tid] = sp;
    __syncthreads();
    for (int s = 128; s > 0; s >>= 1) {
        if (tid < s) s_redf[tid] += s_redf[tid + s];
        __syncthreads();
    }
    if (tid == 0) s_spos = s_redf[0];

    const int npos = g_num_pos[b];
    int k = 3 * npos;
    if (k > PP - 1) k = PP - 1;

    float T = 0.0f;
    if (k > 0) {
        if (tid == 0) { s_prefix = 0u; s_rem = k; }
        __syncthreads();
        for (int shift = 24; shift >= 0; shift -= 8) {
            s_hist[tid] = 0;
            __syncthreads();
            const unsigned pref = s_prefix;
            const int rem = s_rem;
            const unsigned hm = (shift == 24) ? 0u : (0xFFFFFFFFu << (shift + 8));
            for (int p = tid; p < PP; p += 256) {
                unsigned bits = __float_as_uint(s_lm[p]);
                if ((bits & hm) == pref)
                    atomicAdd(&s_hist[(bits >> shift) & 255], 1);
            }
            __syncthreads();
            // parallel suffix scan: s_cum[i] = sum_{j>=i} hist[j]
            s_cum[tid] = s_hist[tid];
            __syncthreads();
            for (int off = 1; off < 256; off <<= 1) {
                int v = (tid + off < 256) ? s_cum[tid + off] : 0;
                __syncthreads();
                s_cum[tid] += v;
                __syncthreads();
            }
            const int above = (tid == 255) ? 0 : s_cum[tid + 1];
            if (s_cum[tid] >= rem && above < rem) {
                s_prefix = pref | ((unsigned)tid << shift);
                s_rem = rem - above;
            }
            __syncthreads();
        }
        const unsigned t = s_prefix;
        float sumgt = 0.0f;
        int cntgt = 0;
        for (int p = tid; p < PP; p += 256) {
            const float lm = s_lm[p];
            if (__float_as_uint(lm) > t) { sumgt += lm; cntgt++; }
        }
        s_redf[tid] = sumgt;
        s_redi[tid] = cntgt;
        __syncthreads();
        for (int s = 128; s > 0; s >>= 1) {
            if (tid < s) {
                s_redf[tid] += s_redf[tid + s];
                s_redi[tid] += s_redi[tid + s];
            }
            __syncthreads();
        }
        T = s_redf[0] + (float)(k - s_redi[0]) * __uint_as_float(t);
    }
    if (tid == 0)
        g_loss_c[b] = s_spos + T;
}

// ---------------- kernel 5: finalize ----------------
__global__ void k_final(float* __restrict__ out) {
    const int tid = threadIdx.x;
    __shared__ float s_l[64], s_c2[64];
    __shared__ int s_n[64];
    s_l[tid] = g_loss_l[tid];
    s_c2[tid] = g_loss_c[tid];
    s_n[tid] = g_num_pos[tid];
    __syncthreads();
    for (int s = 32; s > 0; s >>= 1) {
        if (tid < s) {
            s_l[tid] += s_l[tid + s];
            s_c2[tid] += s_c2[tid + s];
            s_n[tid] += s_n[tid + s];
        }
        __syncthreads();
    }
    if (tid == 0) {
        float n = fmaxf((float)s_n[0], 1.0f);
        out[0] = s_l[0] / n;
        out[1] = s_c2[0] / n;
    }
}

extern "C" void kernel_launch(void* const* d_in, const int* in_sizes, int n_in,
                              void* d_out, int out_size) {
    const float* loc = (const float*)d_in[0];
    const float* conf = (const float*)d_in[1];
    const float* priors = (const float*)d_in[2];
    const float* targets = (const float*)d_in[3];
    float* out = (float*)d_out;

    k_init<<<1, 256>>>();
    k_matchA<<<dim3(BN, NCHUNK), 256>>>(priors, targets);
    k_fix<<<1, 64>>>();
    k_ce<<<dim3((PP + ROWS - 1) / ROWS, BN), ROWS>>>(conf, loc, priors, targets);
    k_topk<<<BN, 256>>>();
    k_final<<<1, 64>>>(out);
}

// round 3
// speedup vs baseline: 1.7973x; 1.3648x over previous
#include <cuda_runtime.h>
#include <cstdint>

#define BN 64
#define PP 8732
#define CC 81
#define KT 16
#define THRESH 0.5f
#define VAR0 0.1f
#define VAR1 0.2f

#define ROWS 128            // rows per CE tile
#define TILES 69            // ceil(PP/ROWS)
#define NCH 16              // matchA chunks per image
#define CHUNK 546           // ceil(PP/NCH)
#define MBLK (BN * NCH)     // 1024 matchA blocks

// ---------------- scratch ----------------
__device__ float g_bto[BN * PP];
__device__ int   g_bti[BN * PP];
__device__ float g_lse[BN * PP];
__device__ float g_lm[BN * PP];     // lse - row[0]  (loss_mine for negatives)
__device__ unsigned long long g_best[BN * KT];  // idempotent atomicMax accumulator
__device__ float g_loss_l[BN];
__device__ float g_loss_c[BN];
__device__ int   g_num_pos[BN];

// ---------------- PTX helpers ----------------
static __device__ __forceinline__ unsigned su32(const void* p) {
    return (unsigned)__cvta_generic_to_shared(p);
}
#define MBAR_INIT(a, c) \
    asm volatile("mbarrier.init.shared.b64 [%0], %1;" :: "r"(a), "r"(c) : "memory")
#define MBAR_EXPECT(a, n) \
    asm volatile("mbarrier.arrive.expect_tx.shared.b64 _, [%0], %1;" :: "r"(a), "r"(n) : "memory")
#define BULK_G2S(dst, src, n, mbar) \
    asm volatile("cp.async.bulk.shared::cta.global.mbarrier::complete_tx::bytes [%0], [%1], %2, [%3];" \
                 :: "r"(dst), "l"(src), "r"(n), "r"(mbar) : "memory")
#define MBAR_WAIT0(a) do {                                                          \
    unsigned _done = 0;                                                             \
    while (!_done) {                                                                \
        asm volatile("{\n\t.reg .pred p;\n\t"                                       \
            "mbarrier.try_wait.parity.acquire.cta.shared::cta.b64 p, [%1], 0, 0x989680;\n\t" \
            "selp.b32 %0, 1, 0, p;\n\t}"                                            \
            : "=r"(_done) : "r"(a) : "memory");                                     \
    }                                                                               \
} while (0)

// ---------------- kernel 1: fused matchA + CE ----------------
__global__ __launch_bounds__(128) void k_big(const float* __restrict__ conf,
                                             const float* __restrict__ priors,
                                             const float* __restrict__ targets) {
    __shared__ __align__(16) float s_c[ROWS * CC];   // 41472 B (CE role)
    __shared__ float s_t[KT][4];
    __shared__ float s_area[KT];
    __shared__ unsigned long long s_best[KT];
    __shared__ __align__(8) unsigned long long s_mbar;

    const int blk = blockIdx.x;
    const int tid = threadIdx.x;

    if (blk < MBLK) {
        // ------- matchA role -------
        const int b = blk >> 4;
        const int c = blk & 15;
        if (tid < KT) {
            const float* tg = targets + (size_t)(b * KT + tid) * 6;
            s_t[tid][0] = tg[2]; s_t[tid][1] = tg[3];
            s_t[tid][2] = tg[4]; s_t[tid][3] = tg[5];
            s_area[tid] = (tg[4] - tg[2]) * (tg[5] - tg[3]);
            s_best[tid] = 0ull;
        }
        __syncthreads();

        const int p0 = c * CHUNK;
        const int p1 = (p0 + CHUNK < PP) ? p0 + CHUNK : PP;

        float bk_ov[KT];
        int   bk_p[KT];
#pragma unroll
        for (int k = 0; k < KT; k++) { bk_ov[k] = -1.0f; bk_p[k] = 0; }

        for (int p = p0 + tid; p < p1; p += 128) {
            const float4 pr = ((const float4*)priors)[p];
            const float parea = (pr.z - pr.x) * (pr.w - pr.y);
            float bestov = -1.0f;
            int besti = 0;
#pragma unroll
            for (int k = 0; k < KT; k++) {
                float ix = fminf(s_t[k][2], pr.z) - fmaxf(s_t[k][0], pr.x);
                float iy = fminf(s_t[k][3], pr.w) - fmaxf(s_t[k][1], pr.y);
                float inter = fmaxf(ix, 0.0f) * fmaxf(iy, 0.0f);
                float ov = inter / (s_area[k] + parea - inter);
                if (ov > bestov) { bestov = ov; besti = k; }     // first-max over k
                if (ov > bk_ov[k]) { bk_ov[k] = ov; bk_p[k] = p; } // first-max over p (asc)
            }
            g_bto[b * PP + p] = bestov;
            g_bti[b * PP + p] = besti;
        }
#pragma unroll
        for (int k = 0; k < KT; k++) {
            unsigned long long key =
                ((unsigned long long)__float_as_uint(bk_ov[k]) << 32) |
                (unsigned long long)(0xFFFFFFFFu - (unsigned)bk_p[k]);
            atomicMax(&s_best[k], key);
        }
        __syncthreads();
        if (tid < KT)
            atomicMax(&g_best[b * KT + tid], s_best[tid]);
    } else {
        // ------- CE role: lse + lm via TMA bulk staging -------
        const int q = blk - MBLK;
        const int b = q / TILES;
        const int tile = q - b * TILES;
        const int r0 = tile * ROWS;
        const int nvalid = (r0 + ROWS <= PP) ? ROWS : (PP - r0);
        const unsigned nbytes = (unsigned)(nvalid * CC * 4);
        const size_t base = ((size_t)b * PP + r0) * CC;

        const unsigned mb = su32(&s_mbar);
        if (tid == 0) MBAR_INIT(mb, 1);
        __syncthreads();
        if (tid == 0) {
            MBAR_EXPECT(mb, nbytes);
            BULK_G2S(su32(s_c), conf + base, nbytes, mb);
        }
        MBAR_WAIT0(mb);

        if (tid < nvalid) {
            const float* row = s_c + tid * CC;
            float s0 = 0.0f, s1 = 0.0f, s2 = 0.0f, s3 = 0.0f;
#pragma unroll 5
            for (int i = 0; i + 3 < CC; i += 4) {
                s0 += __expf(row[i]);
                s1 += __expf(row[i + 1]);
                s2 += __expf(row[i + 2]);
                s3 += __expf(row[i + 3]);
            }
            s0 += __expf(row[CC - 1]);
            const float lse = __logf((s0 + s1) + (s2 + s3));
            const int idx = b * PP + r0 + tid;
            g_lse[idx] = lse;
            g_lm[idx] = lse - row[0];
        }
    }
}

// ---------------- kernel 2: force-assign + conf_t + smooth-L1 + pos-CE + topk ----------------
__global__ __launch_bounds__(256) void k_post(const float* __restrict__ conf,
                                              const float* __restrict__ loc,
                                              const float* __restrict__ priors,
                                              const float* __restrict__ targets) {
    const int b = blockIdx.x;
    const int tid = threadIdx.x;
    const int bPP = b * PP;

    __shared__ __align__(16) float s_lm[PP];   // 34928 B
    __shared__ int s_hist[256];
    __shared__ int s_cum[256];
    __shared__ float s_redf[256];
    __shared__ int s_redi[256];
    __shared__ float s_t[KT][4];
    __shared__ int s_lab[KT];
    __shared__ unsigned s_prefix;
    __shared__ int s_rem;
    __shared__ float s_spos;
    __shared__ __align__(8) unsigned long long s_mbar;

    const unsigned mb = su32(&s_mbar);
    if (tid == 0) MBAR_INIT(mb, 1);
    if (tid < KT) {
        const float* tg = targets + (size_t)(b * KT + tid) * 6;
        s_lab[tid] = (int)tg[1];
        s_t[tid][0] = tg[2]; s_t[tid][1] = tg[3];
        s_t[tid][2] = tg[4]; s_t[tid][3] = tg[5];
    }
    __syncthreads();
    if (tid == 0) {
        MBAR_EXPECT(mb, (unsigned)(PP * 4));
        BULK_G2S(su32(s_lm), g_lm + bPP, (unsigned)(PP * 4), mb);
        // sequential force-assign (last write wins over k), into global (own image only)
        for (int k = 0; k < KT; k++) {
            unsigned long long key = g_best[b * KT + k];
            int p = (int)(0xFFFFFFFFu - (unsigned)(key & 0xFFFFFFFFull));
            float ov = __uint_as_float((unsigned)(key >> 32));
            g_bti[bPP + p] = k;
            g_bto[bPP + p] = ov;
        }
    }
    __syncthreads();   // orders thread-0 global writes for the block
    MBAR_WAIT0(mb);

    // main pass
    float lsum = 0.0f, spos = 0.0f;
    int cnt = 0;
    for (int p = tid; p < PP; p += 256) {
        const float ov = g_bto[bPP + p];
        const int k = g_bti[bPP + p];
        const int ct = (ov < THRESH) ? 0 : s_lab[k];
        if (ct > 0) {
            cnt++;
            s_lm[p] = 0.0f;
            const float lse = g_lse[bPP + p];
            const float gth = conf[(size_t)(bPP + p) * CC + ct];
            spos += lse - gth;
            const float4 pr = ((const float4*)priors)[p];
            const float pcx = 0.5f * (pr.x + pr.z), pcy = 0.5f * (pr.y + pr.w);
            const float pw = pr.z - pr.x, ph = pr.w - pr.y;
            const float mx1 = s_t[k][0], my1 = s_t[k][1];
            const float mx2 = s_t[k][2], my2 = s_t[k][3];
            float g0 = (0.5f * (mx1 + mx2) - pcx) / (VAR0 * pw);
            float g1 = (0.5f * (my1 + my2) - pcy) / (VAR0 * ph);
            float g2 = logf((mx2 - mx1) / pw) / VAR1;
            float g3 = logf((my2 - my1) / ph) / VAR1;
            const float4 ld = ((const float4*)loc)[bPP + p];
            float d, ad;
            d = ld.x - g0; ad = fabsf(d); lsum += (ad < 1.0f) ? 0.5f * d * d : ad - 0.5f;
            d = ld.y - g1; ad = fabsf(d); lsum += (ad < 1.0f) ? 0.5f * d * d : ad - 0.5f;
            d = ld.z - g2; ad = fabsf(d); lsum += (ad < 1.0f) ? 0.5f * d * d : ad - 0.5f;
            d = ld.w - g3; ad = fabsf(d); lsum += (ad < 1.0f) ? 0.5f * d * d : ad - 0.5f;
        }
    }
    // reductions: cnt, spos, lsum
    s_redi[tid] = cnt;
    s_redf[tid] = spos;
    __syncthreads();
    for (int s = 128; s > 0; s >>= 1) {
        if (tid < s) { s_redi[tid] += s_redi[tid + s]; s_redf[tid] += s_redf[tid + s]; }
        __syncthreads();
    }
    const int npos = s_redi[0];
    if (tid == 0) s_spos = s_redf[0];
    __syncthreads();
    s_redf[tid] = lsum;
    __syncthreads();
    for (int s = 128; s > 0; s >>= 1) {
        if (tid < s) s_redf[tid] += s_redf[tid + s];
        __syncthreads();
    }
    if (tid == 0) {
        g_loss_l[b] = s_redf[0];
        g_num_pos[b] = npos;
    }

    int k = 3 * npos;
    if (k > PP - 1) k = PP - 1;

    float T = 0.0f;
    if (k > 0) {
        if (tid == 0) { s_prefix = 0u; s_rem = k; }
        __syncthreads();
        for (int shift = 24; shift >= 0; shift -= 8) {
            s_hist[tid] = 0;
            __syncthreads();
            const unsigned pref = s_prefix;
            const int rem = s_rem;
            const unsigned hm = (shift == 24) ? 0u : (0xFFFFFFFFu << (shift + 8));
            for (int p = tid; p < PP; p += 256) {
                unsigned bits = __float_as_uint(s_lm[p]);
                if ((bits & hm) == pref)
                    atomicAdd(&s_hist[(bits >> shift) & 255], 1);
            }
            __syncthreads();
            s_cum[tid] = s_hist[tid];
            __syncthreads();
            for (int off = 1; off < 256; off <<= 1) {
                int v = (tid + off < 256) ? s_cum[tid + off] : 0;
                __syncthreads();
                s_cum[tid] += v;
                __syncthreads();
            }
            const int above = (tid == 255) ? 0 : s_cum[tid + 1];
            if (s_cum[tid] >= rem && above < rem) {
                s_prefix = pref | ((unsigned)tid << shift);
                s_rem = rem - above;
            }
            __syncthreads();
        }
        const unsigned t = s_prefix;
        float sumgt = 0.0f;
        int cntgt = 0;
        for (int p = tid; p < PP; p += 256) {
            const float lm = s_lm[p];
            if (__float_as_uint(lm) > t) { sumgt += lm; cntgt++; }
        }
        s_redf[tid] = sumgt;
        s_redi[tid] = cntgt;
        __syncthreads();
        for (int s = 128; s > 0; s >>= 1) {
            if (tid < s) { s_redf[tid] += s_redf[tid + s]; s_redi[tid] += s_redi[tid + s]; }
            __syncthreads();
        }
        T = s_redf[0] + (float)(k - s_redi[0]) * __uint_as_float(t);
    }
    if (tid == 0)
        g_loss_c[b] = s_spos + T;
}

// ---------------- kernel 3: finalize ----------------
__global__ void k_final(float* __restrict__ out) {
    const int tid = threadIdx.x;
    __shared__ float s_l[64], s_c2[64];
    __shared__ int s_n[64];
    s_l[tid] = g_loss_l[tid];
    s_c2[tid] = g_loss_c[tid];
    s_n[tid] = g_num_pos[tid];
    __syncthreads();
    for (int s = 32; s > 0; s >>= 1) {
        if (tid < s) {
            s_l[tid] += s_l[tid + s];
            s_c2[tid] += s_c2[tid + s];
            s_n[tid] += s_n[tid + s];
        }
        __syncthreads();
    }
    if (tid == 0) {
        float n = fmaxf((float)s_n[0], 1.0f);
        out[0] = s_l[0] / n;
        out[1] = s_c2[0] / n;
    }
}

extern "C" void kernel_launch(void* const* d_in, const int* in_sizes, int n_in,
                              void* d_out, int out_size) {
    const float* loc = (const float*)d_in[0];
    const float* conf = (const float*)d_in[1];
    const float* priors = (const float*)d_in[2];
    const float* targets = (const float*)d_in[3];
    float* out = (float*)d_out;

    k_big<<<MBLK + BN * TILES, 128>>>(conf, priors, targets);
    k_post<<<BN, 256>>>(conf, loc, priors, targets);
    k_final<<<1, 64>>>(out);
}